// round 15
// baseline (speedup 1.0000x reference)
#include <cuda_runtime.h>
#include <cuda_bf16.h>
#include <math.h>

// ---------------- problem constants ----------------
#define BB 4
#define TT_SEQ 4096
#define DD 1024
#define NTOK (BB*TT_SEQ)          // 16384
#define NBLK 16
#define BIP 192
#define RANKR 64
#define NMEM 128
#define EPSV 1.1920929e-07f
#define NT128 (NTOK/128)          // 128
#define NPOS 32
#define NCHAIN 64

// fragment-slot strides
#define ASLOT 132
#define BSLOT2 132                // k-paired B slot: 32 lanes * 4 uints + pad
#define BSZ (16*BSLOT2)           // 2112 uints per 64x64 B tile (16 slots)
#define ASZ64  (16*ASLOT)
#define ASZ128 (32*ASLOT)         // 4224 uints
#define ARSZ 4096                 // row-major A tile: 128 rows x 128B
#define SDS 66

// ---------------- scratch (device globals; no allocation) ----------------
__device__ __nv_bfloat16 g_xn   [NTOK*DD];
__device__ __nv_bfloat16 g_hn   [NTOK*DD];
__device__ float g_rsx  [NTOK];
__device__ float g_rsh  [NTOK];

// decoupled-lookback state
__device__ int   g_ticket;
__device__ int   g_state[NCHAIN*NPOS];
__device__ float g_aggv [NCHAIN*NPOS*64];
__device__ float g_incv [NCHAIN*NPOS*64];

// fragment-major activations (A-layout, unchanged)
__device__ uint4 g_rf[NT128*16*(ASZ128/4)];
__device__ uint4 g_tf[NT128*(ASZ128/4)];

// pre-fragmented bf16 weights (k-paired B layout)
__device__ uint4 g_wf_seq [NBLK*BSZ/4];
__device__ uint4 g_wf_dep [NBLK*BSZ/4];
__device__ uint4 g_wf_loc [NBLK*BSZ/4];
__device__ uint4 g_wf_lrA [NBLK*BSZ/4];
__device__ uint4 g_wf_post[NBLK*3*BSZ/4];
__device__ uint4 g_wf_lrB [16*BSZ/4];

__device__ __forceinline__ float siluf(float x) {
    return x / (1.0f + __expf(-x));
}

__device__ __forceinline__ unsigned pk(float a, float b) {
    unsigned r;
    asm("cvt.rn.bf16x2.f32 %0, %1, %2;" : "=r"(r) : "f"(b), "f"(a));
    return r;
}

__device__ __forceinline__ float decay1(const float* __restrict__ lA,
                                        const float* __restrict__ ldt, int d) {
    return fmaxf(__expf(-__expf(lA[d]) * __expf(ldt[d])), 1e-6f);
}

// ---------------- acquire/release ----------------
__device__ __forceinline__ int ld_acq(const int* p) {
    int v;
    asm volatile("ld.global.acquire.gpu.b32 %0, [%1];" : "=r"(v) : "l"(p));
    return v;
}
__device__ __forceinline__ void st_rel(int* p, int v) {
    asm volatile("st.global.release.gpu.b32 [%0], %1;" :: "l"(p), "r"(v));
}

// ---------------- cp.async helpers ----------------
__device__ __forceinline__ unsigned sptr(const void* p) {
    return (unsigned)__cvta_generic_to_shared(p);
}
__device__ __forceinline__ void cpa16(unsigned d, const void* s) {
    asm volatile("cp.async.cg.shared.global [%0], [%1], 16;" :: "r"(d), "l"(s));
}
__device__ __forceinline__ void cpa16z(unsigned d, const void* s) {
    asm volatile("cp.async.cg.shared.global [%0], [%1], 16, 0;" :: "r"(d), "l"(s));
}
__device__ __forceinline__ void cp_commit() {
    asm volatile("cp.async.commit_group;");
}
template<int N>
__device__ __forceinline__ void cp_wait() {
    asm volatile("cp.async.wait_group %0;" :: "n"(N));
}
template<int N4>
__device__ __forceinline__ void cpcopy(unsigned dsm, const uint4* __restrict__ src, int tid) {
#pragma unroll
    for (int i = tid; i < N4; i += 256) cpa16(dsm + i * 16, src + i);
}

// row-major A chunk copy: 128 tokens x 64 bf16 (128B/row), SW128 swizzle.
template<bool SHIFT>
__device__ __forceinline__ void cpA_row(unsigned dsm, const __nv_bfloat16* __restrict__ colbase,
                                        int tok0, int tid) {
#pragma unroll
    for (int it = 0; it < 4; ++it) {
        int idx = tid + it * 256;
        int row = idx >> 3;
        int c16 = idx & 7;
        unsigned dst = dsm + row * 128 + ((c16 ^ (row & 7)) << 4);
        int tok = tok0 + row;
        if (SHIFT) {
            if ((tok & (TT_SEQ - 1)) == 0) cpa16z(dst, colbase);
            else cpa16(dst, colbase + (size_t)(tok - 1) * DD + c16 * 8);
        } else {
            cpa16(dst, colbase + (size_t)tok * DD + c16 * 8);
        }
    }
}

// ---------------- bf16 MMA machinery ----------------
__device__ __forceinline__ void mma_bf16(float c[4], const unsigned a[4],
                                         unsigned b0, unsigned b1) {
    asm volatile("mma.sync.aligned.m16n8k16.row.col.f32.bf16.bf16.f32 "
        "{%0,%1,%2,%3}, {%4,%5,%6,%7}, {%8,%9}, {%0,%1,%2,%3};"
        : "+f"(c[0]), "+f"(c[1]), "+f"(c[2]), "+f"(c[3])
        : "r"(a[0]), "r"(a[1]), "r"(a[2]), "r"(a[3]), "r"(b0), "r"(b1));
}

// ldmatrix x4: A fragment (m16 tile mt, k-chunk ks) from swizzled row-major tile
__device__ __forceinline__ void ldsmA(unsigned a[4], unsigned sAbase, int mt, int ks, int lane) {
    int row = mt * 16 + (lane & 7) + ((lane & 8) ? 8 : 0);
    int ci  = ks * 2 + ((lane & 16) ? 1 : 0);
    unsigned addr = sAbase + row * 128 + ((ci ^ (row & 7)) << 4);
    asm volatile("ldmatrix.sync.aligned.m8n8.x4.shared.b16 {%0,%1,%2,%3}, [%4];"
        : "=r"(a[0]), "=r"(a[1]), "=r"(a[2]), "=r"(a[3]) : "r"(addr));
}

// M=128 mma over row-major A (ldmatrix) and k-paired B
__device__ __forceinline__ void mma_chunk128_lm(float acc[8][4], unsigned sAbase,
                                                const unsigned* sB, int w, int lane) {
#pragma unroll
    for (int ks2 = 0; ks2 < 2; ks2++) {
        unsigned a0[4], a1[4];
        ldsmA(a0, sAbase, w, ks2 * 2, lane);
        ldsmA(a1, sAbase, w, ks2 * 2 + 1, lane);
#pragma unroll
        for (int nt = 0; nt < 8; nt++) {
            uint4 b4 = *reinterpret_cast<const uint4*>(&sB[(nt * 2 + ks2) * BSLOT2 + lane * 4]);
            mma_bf16(acc[nt], a0, b4.x, b4.y);
            mma_bf16(acc[nt], a1, b4.z, b4.w);
        }
    }
}

// M=64 fragment-major mma (g3 path)
__device__ __forceinline__ void mma_chunk64(float acc[4][4], const unsigned* sA,
                                            const unsigned* sB, int wm, int wn, int lane) {
#pragma unroll
    for (int ks2 = 0; ks2 < 2; ks2++) {
        unsigned a0[4], a1[4];
        *reinterpret_cast<uint4*>(a0) =
            *reinterpret_cast<const uint4*>(&sA[(wm * 4 + ks2 * 2) * ASLOT + lane * 4]);
        *reinterpret_cast<uint4*>(a1) =
            *reinterpret_cast<const uint4*>(&sA[(wm * 4 + ks2 * 2 + 1) * ASLOT + lane * 4]);
#pragma unroll
        for (int nt = 0; nt < 4; nt++) {
            uint4 b4 = *reinterpret_cast<const uint4*>(
                &sB[((wn * 4 + nt) * 2 + ks2) * BSLOT2 + lane * 4]);
            mma_bf16(acc[nt], a0, b4.x, b4.y);
            mma_bf16(acc[nt], a1, b4.z, b4.w);
        }
    }
}

// M=128 fragment-major mma (g4 path)
__device__ __forceinline__ void mma_chunk128_frag(float acc[8][4], const unsigned* sA,
                                                  const unsigned* sB, int w, int lane) {
#pragma unroll
    for (int ks2 = 0; ks2 < 2; ks2++) {
        unsigned a0[4], a1[4];
        *reinterpret_cast<uint4*>(a0) =
            *reinterpret_cast<const uint4*>(&sA[(w * 4 + ks2 * 2) * ASLOT + lane * 4]);
        *reinterpret_cast<uint4*>(a1) =
            *reinterpret_cast<const uint4*>(&sA[(w * 4 + ks2 * 2 + 1) * ASLOT + lane * 4]);
#pragma unroll
        for (int nt = 0; nt < 8; nt++) {
            uint4 b4 = *reinterpret_cast<const uint4*>(&sB[(nt * 2 + ks2) * BSLOT2 + lane * 4]);
            mma_bf16(acc[nt], a0, b4.x, b4.y);
            mma_bf16(acc[nt], a1, b4.z, b4.w);
        }
    }
}

__device__ __forceinline__ void scale_acc(float acc[8][4], float ra, float rb) {
#pragma unroll
    for (int nt = 0; nt < 8; nt++) {
        acc[nt][0] *= ra; acc[nt][1] *= ra;
        acc[nt][2] *= rb; acc[nt][3] *= rb;
    }
}

// ---------------- prep: flags + weight fragmentation (k-paired B) + x stats ----------------
__global__ void __launch_bounds__(256) k_prep(const float* __restrict__ x,
                                              const float* __restrict__ wseq,
                                              const float* __restrict__ wdep,
                                              const float* __restrict__ wloc,
                                              const float* __restrict__ lrA,
                                              const float* __restrict__ wpost,
                                              const float* __restrict__ lrB) {
    int tid = threadIdx.x;
    if (blockIdx.x == 0) {
        if (tid == 0) g_ticket = 0;
        for (int i = tid; i < NCHAIN * NPOS; i += 256) g_state[i] = 0;
    }
    if (blockIdx.x < 128) {
        int t = blockIdx.x;
        const float* src;
        unsigned* dst;
        int rs;
        if (t < 16)       { src = wseq + (size_t)t * 4096; dst = (unsigned*)g_wf_seq + t * BSZ; rs = 64; }
        else if (t < 32)  { int b = t - 16; src = wdep + (size_t)b * 4096; dst = (unsigned*)g_wf_dep + b * BSZ; rs = 64; }
        else if (t < 48)  { int b = t - 32; src = wloc + (size_t)b * 4096; dst = (unsigned*)g_wf_loc + b * BSZ; rs = 64; }
        else if (t < 64)  { int b = t - 48; src = lrA + (size_t)b * 4096;  dst = (unsigned*)g_wf_lrA + b * BSZ; rs = 64; }
        else if (t < 112) { int i = t - 64; int b = i / 3, kt = i % 3;
                            src = wpost + (size_t)b * 64 * BIP + kt * 64;
                            dst = (unsigned*)g_wf_post + i * BSZ; rs = BIP; }
        else              { int kt = t - 112; src = lrB + kt * 64; dst = (unsigned*)g_wf_lrB + kt * BSZ; rs = DD; }
#pragma unroll
        for (int it = 0; it < 4; ++it) {
            int idx = tid + it * 256;
            int n  = idx >> 4;
            int k0 = (idx & 15) << 2;
            float4 v = *reinterpret_cast<const float4*>(src + (size_t)n * rs + k0);
            int nt = n >> 3, g = n & 7;
            int ks = k0 >> 4, kk = k0 & 15, hi = kk >> 3, t0 = (kk & 7) >> 1;
            // k-paired layout: slot (nt*2 + ks/2), within: lane*4 + (ks&1)*2 + hi
            unsigned* p = &dst[(nt * 2 + (ks >> 1)) * BSLOT2 + (g * 4 + t0) * 4 + (ks & 1) * 2 + hi];
            p[0] = pk(v.x, v.y);
            p[4] = pk(v.z, v.w);     // t0+1 lane, +4 uints
        }
    } else {
        int w = tid >> 5, lane = tid & 31;
        int tok = (blockIdx.x - 128) * 8 + w;
        const float4* xr = reinterpret_cast<const float4*>(x + (size_t)tok * DD);
        float4 v[8];
        float ss = 0.0f;
#pragma unroll
        for (int i = 0; i < 8; i++) {
            v[i] = xr[lane + i * 32];
            ss += v[i].x * v[i].x + v[i].y * v[i].y + v[i].z * v[i].z + v[i].w * v[i].w;
        }
#pragma unroll
        for (int off = 16; off > 0; off >>= 1) ss += __shfl_xor_sync(0xffffffffu, ss, off);
        ss = __shfl_sync(0xffffffffu, ss, 0);
        float sc = rsqrtf(ss * (1.0f / DD) + EPSV);
        if (lane == 0) g_rsx[tok] = sc;
        uint2* xo = reinterpret_cast<uint2*>(g_xn + (size_t)tok * DD);
#pragma unroll
        for (int i = 0; i < 8; i++) {
            uint2 o;
            o.x = pk(v[i].x * sc, v[i].y * sc);
            o.y = pk(v[i].z * sc, v[i].w * sc);
            xo[lane + i * 32] = o;
        }
    }
}

// ---------------- gain helper ----------------
__device__ __forceinline__ float gain_of(int gch, float Kf, const float* __restrict__ lAd,
                                         const float* __restrict__ ldtd) {
    if (gch < NMEM) return Kf;
    float a1 = __expf(-__expf(lAd[gch - NMEM]) * __expf(ldtd[gch - NMEM]));
    float om = 1.0f - a1;
    if (fabsf(om) < 1e-6f) return Kf;
    return (1.0f - __expf(Kf * __logf(a1))) / fmaxf(om, 1e-8f);
}

// ---------------- G1S: GEMMs (ldmatrix A, k-paired B) + single-pass scan -> g_hn ----------------
#define G1SMEM (13248 * 4)

__global__ void __launch_bounds__(256) k_g1s(const float* __restrict__ lAd,
                                             const float* __restrict__ ldtd,
                                             const float* __restrict__ lAs,
                                             const float* __restrict__ ldts,
                                             const int* __restrict__ kptr) {
    extern __shared__ __align__(16) unsigned dyn[];
    __shared__ int s_ticket;
    int tid = threadIdx.x, lane = tid & 31, w = tid >> 5;

    if (tid == 0) s_ticket = atomicAdd(&g_ticket, 1);
    __syncthreads();
    int ticket = s_ticket;
    int chain = ticket & (NCHAIN - 1);
    int pos   = ticket >> 6;
    int b = chain >> 4, blk = chain & 15;
    int tok0 = (b * NPOS + pos) * 128;

    unsigned* sB1 = dyn + ARSZ;
    unsigned* sB2 = dyn + ARSZ + BSZ;

    cpA_row<false>(sptr(dyn), g_xn + blk * 64, tok0, tid);
    cpcopy<528>(sptr(sB1), g_wf_seq + (size_t)blk * 528, tid);
    cpcopy<528>(sptr(sB2), g_wf_dep + (size_t)blk * 528, tid);
    cp_commit();
    cp_wait<0>();
    __syncthreads();

    float as_[8][4] = {}, ad_[8][4] = {};
    unsigned sAbase = sptr(dyn);
#pragma unroll
    for (int ks2 = 0; ks2 < 2; ks2++) {
        unsigned a0[4], a1[4];
        ldsmA(a0, sAbase, w, ks2 * 2, lane);
        ldsmA(a1, sAbase, w, ks2 * 2 + 1, lane);
#pragma unroll
        for (int nt = 0; nt < 8; nt++) {
            int off = (nt * 2 + ks2) * BSLOT2 + lane * 4;
            uint4 b1 = *reinterpret_cast<const uint4*>(&sB1[off]);
            uint4 b2 = *reinterpret_cast<const uint4*>(&sB2[off]);
            mma_bf16(as_[nt], a0, b1.x, b1.y);
            mma_bf16(as_[nt], a1, b1.z, b1.w);
            mma_bf16(ad_[nt], a0, b2.x, b2.y);
            mma_bf16(ad_[nt], a1, b2.z, b2.w);
        }
    }
    __syncthreads();                  // staging dead; alias scan buffers

    float*    sD  = reinterpret_cast<float*>(dyn);           // [128][66] fp32
    unsigned* sHD = dyn + 8448;                              // [128][33] bf16x2
    float*    sS  = reinterpret_cast<float*>(dyn + 12672);   // [4][64]
    float*    sQ  = sS + 256;                                // [4][64]
    float*    sC  = sQ + 256;                                // [64]

    // epilogue: silu -> drive (fp32, smem) ; gain*silu -> hd (bf16x2, smem)
    {
        float Kf = (float)(*kptr);
        int g = lane >> 2, t = lane & 3;
        int rl0 = w * 16 + g;
#pragma unroll
        for (int nt = 0; nt < 8; nt++) {
            int nl = nt * 8 + t * 2;
            int gch = blk * 64 + nl;
            float gn0 = gain_of(gch, Kf, lAd, ldtd);
            float gn1 = gain_of(gch + 1, Kf, lAd, ldtd);
            *reinterpret_cast<float2*>(&sD[rl0 * SDS + nl]) =
                make_float2(siluf(as_[nt][0]), siluf(as_[nt][1]));
            *reinterpret_cast<float2*>(&sD[(rl0 + 8) * SDS + nl]) =
                make_float2(siluf(as_[nt][2]), siluf(as_[nt][3]));
            sHD[rl0 * 33 + (nl >> 1)] =
                pk(gn0 * siluf(ad_[nt][0]), gn1 * siluf(ad_[nt][1]));
            sHD[(rl0 + 8) * 33 + (nl >> 1)] =
                pk(gn0 * siluf(ad_[nt][2]), gn1 * siluf(ad_[nt][3]));
        }
    }
    __syncthreads();

    // scan thread mapping: ch = tid & 63, q = tid >> 6
    int ch = tid & 63, q = tid >> 6;
    int gch = blk * 64 + ch;
    float a  = decay1(lAs, ldts, gch);
    float la = __logf(a);
    float a32 = __expf(32.0f * la);
    float aT  = __expf(128.0f * la);

    // local quarter scan (in place)
    {
        float y = 0.0f;
        int base = q * 32;
#pragma unroll 8
        for (int s = 0; s < 32; s++) {
            float* p = &sD[(base + s) * SDS + ch];
            y = fmaf(a, y, *p);
            *p = y;
        }
        sS[q * 64 + ch] = y;
    }
    __syncthreads();

    // quarter combine + aggregate publish
    float agg = 0.0f;
    if (tid < 64) {
        float C = 0.0f;
#pragma unroll
        for (int q2 = 0; q2 < 4; q2++) {
            sQ[q2 * 64 + tid] = C;
            C = fmaf(C, a32, sS[q2 * 64 + tid]);
        }
        agg = C;
        g_aggv[(size_t)(chain * NPOS + pos) * 64 + tid] = agg;
    }
    __syncthreads();
    if (tid == 0) {
        __threadfence();
        st_rel(&g_state[chain * NPOS + pos], 1);
    }

    // lookback
    if (tid < 64) {
        float carry = 0.0f;
        if (pos > 0) {
            float f = 1.0f;
            int p = pos - 1;
            while (true) {
                int st;
                do { st = ld_acq(&g_state[chain * NPOS + p]); } while (st == 0);
                if (st == 2) {
                    carry = fmaf(f, g_incv[(size_t)(chain * NPOS + p) * 64 + tid], carry);
                    break;
                }
                carry = fmaf(f, g_aggv[(size_t)(chain * NPOS + p) * 64 + tid], carry);
                f *= aT;
                if (--p < 0) break;
            }
        }
        sC[tid] = carry;
        if (pos < NPOS - 1)
            g_incv[(size_t)(chain * NPOS + pos) * 64 + tid] = fmaf(carry, aT, agg);
    }
    __syncthreads();
    if (tid == 0 && pos < NPOS - 1) {
        __threadfence();
        st_rel(&g_state[chain * NPOS + pos], 2);
    }

    // final combine: h = local + eff_carry * a^(s+1) + hd
    {
        float carry = sC[ch];
        float a64 = a32 * a32;
        float aq = (q == 0) ? 1.0f : (q == 1) ? a32 : (q == 2) ? a64 : a64 * a32;
        float eff = fmaf(carry, aq, sQ[q * 64 + ch]);
        float pw = eff * a;
        int base = q * 32;
#pragma unroll 8
        for (int s = 0; s < 32; s++) {
            int row = base + s;
            unsigned hu = sHD[row * 33 + (ch >> 1)];
            float2 hp = __bfloat1622float2(*reinterpret_cast<__nv_bfloat162*>(&hu));
            float hdv = (ch & 1) ? hp.y : hp.x;
            float* p = &sD[row * SDS + ch];
            *p = *p + pw + hdv;
            pw *= a;
        }
    }
    __syncthreads();

    // pack + coalesced store of h -> g_hn
#pragma unroll
    for (int it = 0; it < 16; it++) {
        int idx = tid + it * 256;
        int row = idx >> 5;
        int c2  = idx & 31;
        float h0 = sD[row * SDS + c2 * 2];
        float h1 = sD[row * SDS + c2 * 2 + 1];
        *reinterpret_cast<unsigned*>(&g_hn[(size_t)(tok0 + row) * DD + blk * 64 + c2 * 2]) =
            pk(h0, h1);
    }
}

// ---------------- rstd: warp-per-token over g_hn -> g_rsh ----------------
__global__ void __launch_bounds__(256) k_rstd() {
    int w = threadIdx.x >> 5, lane = threadIdx.x & 31;
    int tok = blockIdx.x * 8 + w;
    const uint4* hr = reinterpret_cast<const uint4*>(g_hn + (size_t)tok * DD);
    float ss = 0.0f;
#pragma unroll
    for (int i = 0; i < 4; i++) {
        uint4 u = hr[lane + i * 32];
        float2 a0 = __bfloat1622float2(*reinterpret_cast<__nv_bfloat162*>(&u.x));
        float2 a1 = __bfloat1622float2(*reinterpret_cast<__nv_bfloat162*>(&u.y));
        float2 a2 = __bfloat1622float2(*reinterpret_cast<__nv_bfloat162*>(&u.z));
        float2 a3 = __bfloat1622float2(*reinterpret_cast<__nv_bfloat162*>(&u.w));
        ss += a0.x * a0.x + a0.y * a0.y + a1.x * a1.x + a1.y * a1.y
            + a2.x * a2.x + a2.y * a2.y + a3.x * a3.x + a3.y * a3.y;
    }
#pragma unroll
    for (int off = 16; off > 0; off >>= 1) ss += __shfl_xor_sync(0xffffffffu, ss, off);
    if (lane == 0) g_rsh[tok] = rsqrtf(ss * (1.0f / DD) + EPSV);
}

// ---------------- G2: fully-async A (row-major + ldmatrix), acc-side rsh ----------------
__device__ __forceinline__ void g2_cpA(unsigned dsm, int tok0, int gc, int tid) {
    if (gc < 16)      cpA_row<false>(dsm, g_hn + gc * 64, tok0, tid);
    else if (gc < 32) cpA_row<false>(dsm, g_xn + (gc - 16) * 64, tok0, tid);
    else              cpA_row<true >(dsm, g_xn + (gc - 32) * 64, tok0, tid);
}

#define G2SMEM ((2 * ARSZ + 2 * BSZ) * 4)   // 49664 bytes

__global__ void __launch_bounds__(256, 4) k_g2() {
    extern __shared__ __align__(16) unsigned dsm[];
    unsigned* sA0 = dsm;
    unsigned* sA1 = dsm + ARSZ;
    unsigned* sB0 = dsm + 2 * ARSZ;
    unsigned* sB1 = sB0 + BSZ;
    int blk = blockIdx.y;
    int tok0 = blockIdx.x * 128;
    int tid = threadIdx.x, lane = tid & 31, w = tid >> 5;
    const uint4* wp = g_wf_post + (size_t)(blk * 3) * 528;
    int gc0 = blk * 3;

    g2_cpA(sptr(sA0), tok0, gc0 + 0, tid);
    cpcopy<528>(sptr(sB0), wp, tid);
    cp_commit();                              // group0: A0 + B0
    g2_cpA(sptr(sA1), tok0, gc0 + 1, tid);
    cpcopy<528>(sptr(sB1), wp + 528, tid);
    cp_commit();                              // group1: A1 + B1

    int g = lane >> 2, t = lane & 3;
    int r0 = tok0 + w * 16 + g;
    float rsh_a = g_rsh[r0];
    float rsh_b = g_rsh[r0 + 8];
    int hnc = 16 - gc0;
    hnc = hnc < 0 ? 0 : (hnc > 3 ? 3 : hnc);

    float acc[8][4] = {};
    cp_wait<1>();
    __syncthreads();
    mma_chunk128_lm(acc, sptr(sA0), sB0, w, lane);
    if (hnc == 1) scale_acc(acc, rsh_a, rsh_b);
    __syncthreads();

    g2_cpA(sptr(sA0), tok0, gc0 + 2, tid);
    cpcopy<528>(sptr(sB0), wp + 1056, tid);
    cp_commit();                              // group2: A2 + B2

    cp_wait<1>();
    __syncthreads();
    mma_chunk128_lm(acc, sptr(sA1), sB1, w, lane);
    if (hnc == 2) scale_acc(acc, rsh_a, rsh_b);
    __syncthreads();

    cp_wait<0>();
    __syncthreads();
    mma_chunk128_lm(acc, sptr(sA0), sB0, w, lane);
    if (hnc == 3) scale_acc(acc, rsh_a, rsh_b);

    // epilogue -> g_rf (A fragment layout, unchanged)
    unsigned* rf = (unsigned*)g_rf + ((size_t)((tok0 >> 7) * 16 + blk)) * ASZ128;
#pragma unroll
    for (int nt = 0; nt < 8; nt++) {
        int ks = nt >> 1, hi = nt & 1;
        unsigned* p = rf + (w * 4 + ks) * ASLOT + (g * 4 + t) * 4 + 2 * hi;
        p[0] = pk(siluf(acc[nt][0]), siluf(acc[nt][1]));
        p[1] = pk(siluf(acc[nt][2]), siluf(acc[nt][3]));
    }
}

// ---------------- G3: t = r @ lr_B^T (M=64, 2-stage cp.async pipeline) ----------------
__device__ __forceinline__ void g3_issue(unsigned dA, unsigned dB, int slab16, int halfoff,
                                         int kt, int tid) {
    cpcopy<528>(dA, g_rf + (size_t)(slab16 + kt) * 1056 + halfoff, tid);
    cpcopy<528>(dB, g_wf_lrB + (size_t)kt * 528, tid);
    cp_commit();
}

__global__ void __launch_bounds__(256) k_g3() {
    __shared__ __align__(16) unsigned smem[2 * ASZ64 + 2 * BSZ];
    unsigned* sAb[2] = { smem, smem + ASZ64 };
    unsigned* sBb[2] = { smem + 2 * ASZ64, smem + 2 * ASZ64 + BSZ };
    int tok0 = blockIdx.x * 64;
    int tid = threadIdx.x, lane = tid & 31, w = tid >> 5, wm = w & 3, wn = w >> 2;
    int slab16 = (tok0 >> 7) * 16;
    int halfoff = ((tok0 >> 6) & 1) * 528;

    g3_issue(sptr(sAb[0]), sptr(sBb[0]), slab16, halfoff, 0, tid);
    g3_issue(sptr(sAb[1]), sptr(sBb[1]), slab16, halfoff, 1, tid);

    float acc[4][4] = {};
#pragma unroll
    for (int kt = 0; kt < 16; kt++) {
        if (kt < 15) cp_wait<1>(); else cp_wait<0>();
        __syncthreads();
        mma_chunk64(acc, sAb[kt & 1], sBb[kt & 1], wm, wn, lane);
        __syncthreads();
        if (kt + 2 < 16)
            g3_issue(sptr(sAb[kt & 1]), sptr(sBb[kt & 1]), slab16, halfoff, kt + 2, tid);
    }

    int g = lane >> 2, t = lane & 3;
    int mtg = ((tok0 & 64) >> 4) + wm;
    unsigned* tf = (unsigned*)g_tf + (size_t)(tok0 >> 7) * ASZ128;
#pragma unroll
    for (int nt = 0; nt < 4; nt++) {
        int ng = wn * 4 + nt;
        int ks = ng >> 1, hi = ng & 1;
        unsigned* p = tf + (mtg * 4 + ks) * ASLOT + (g * 4 + t) * 4 + 2 * hi;
        p[0] = pk(acc[nt][0], acc[nt][1]);
        p[1] = pk(acc[nt][2], acc[nt][3]);
    }
}

// ---------------- G4: out = x + bd(r, w_local) + t @ lr_A^T (M=128) ----------------
#define G4SMEM (2 * (ASZ128 + BSZ) * 4)

__global__ void __launch_bounds__(256, 4) k_g4(const float* __restrict__ x,
                                               float* __restrict__ out) {
    extern __shared__ __align__(16) unsigned dsm[];
    unsigned* sA0 = dsm;
    unsigned* sB0 = dsm + ASZ128;
    unsigned* sA1 = dsm + ASZ128 + BSZ;
    unsigned* sB1 = dsm + 2 * ASZ128 + BSZ;
    int blk = blockIdx.y;
    int tok0 = blockIdx.x * 128;
    int tid = threadIdx.x, lane = tid & 31, w = tid >> 5;
    int slab16 = (tok0 >> 7) * 16;

    cpcopy<1056>(sptr(sA0), g_rf + (size_t)(slab16 + blk) * 1056, tid);
    cpcopy<528>(sptr(sB0), g_wf_loc + (size_t)blk * 528, tid);
    cp_commit();
    cpcopy<1056>(sptr(sA1), g_tf + (size_t)(tok0 >> 7) * 1056, tid);
    cpcopy<528>(sptr(sB1), g_wf_lrA + (size_t)blk * 528, tid);
    cp_commit();

    float acc[8][4] = {};
    cp_wait<1>();
    __syncthreads();
    mma_chunk128_frag(acc, sA0, sB0, w, lane);
    cp_wait<0>();
    __syncthreads();
    mma_chunk128_frag(acc, sA1, sB1, w, lane);

    int g = lane >> 2, t = lane & 3;
    int r0 = tok0 + w * 16 + g;
#pragma unroll
    for (int nt = 0; nt < 8; nt++) {
        int n = blk * 64 + nt * 8 + t * 2;
        size_t i0 = (size_t)r0 * DD + n;
        size_t i1 = (size_t)(r0 + 8) * DD + n;
        float2 x0 = *reinterpret_cast<const float2*>(&x[i0]);
        float2 x1 = *reinterpret_cast<const float2*>(&x[i1]);
        *reinterpret_cast<float2*>(&out[i0]) = make_float2(x0.x + acc[nt][0], x0.y + acc[nt][1]);
        *reinterpret_cast<float2*>(&out[i1]) = make_float2(x1.x + acc[nt][2], x1.y + acc[nt][3]);
    }
}

// ---------------- launch ----------------
extern "C" void kernel_launch(void* const* d_in, const int* in_sizes, int n_in,
                              void* d_out, int out_size) {
    const float* x    = (const float*)d_in[0];
    const int*   actk = (const int*)  d_in[1];
    const float* wseq = (const float*)d_in[2];
    const float* wdep = (const float*)d_in[3];
    const float* wpost= (const float*)d_in[4];
    const float* wloc = (const float*)d_in[5];
    const float* lrA  = (const float*)d_in[6];
    const float* lrB  = (const float*)d_in[7];
    const float* lAs  = (const float*)d_in[8];
    const float* ldts = (const float*)d_in[9];
    const float* lAd  = (const float*)d_in[10];
    const float* ldtd = (const float*)d_in[11];
    float* out = (float*)d_out;

    static bool attr_done = false;
    if (!attr_done) {
        cudaFuncSetAttribute(k_g1s, cudaFuncAttributeMaxDynamicSharedMemorySize, G1SMEM);
        cudaFuncSetAttribute(k_g2,  cudaFuncAttributeMaxDynamicSharedMemorySize, G2SMEM);
        cudaFuncSetAttribute(k_g4,  cudaFuncAttributeMaxDynamicSharedMemorySize, G4SMEM);
        attr_done = true;
    }

    dim3 gGemm(NTOK / 128, NBLK);    // (128, 16)

    k_prep<<<128 + NTOK / 8, 256>>>(x, wseq, wdep, wloc, lrA, wpost, lrB);
    k_g1s<<<NT128 * 16, 256, G1SMEM>>>(lAd, ldtd, lAs, ldts, actk);
    k_rstd<<<NTOK / 8, 256>>>();
    k_g2<<<gGemm, 256, G2SMEM>>>();
    k_g3<<<NTOK / 64, 256>>>();
    k_g4<<<gGemm, 256, G4SMEM>>>(x, out);
}

// round 16
// speedup vs baseline: 1.0379x; 1.0379x over previous
#include <cuda_runtime.h>
#include <cuda_bf16.h>
#include <math.h>

// ---------------- problem constants ----------------
#define BB 4
#define TT_SEQ 4096
#define DD 1024
#define NTOK (BB*TT_SEQ)          // 16384
#define NBLK 16
#define BIP 192
#define RANKR 64
#define NMEM 128
#define EPSV 1.1920929e-07f
#define NT128 (NTOK/128)          // 128
#define NPOS 32
#define NCHAIN 64

// fragment-slot strides
#define ASLOT 132
#define BSLOT 66
#define BSZ (32*BSLOT)            // 2112 uints
#define ASZ64  (16*ASLOT)
#define ASZ128 (32*ASLOT)         // 4224 uints
#define ARSZ 4096                 // row-major A tile: 128 rows x 128B
#define SDS 66

// ---------------- scratch (device globals; no allocation) ----------------
__device__ __nv_bfloat16 g_xn   [NTOK*DD];
__device__ __nv_bfloat16 g_hn   [NTOK*DD];
__device__ float g_rsx  [NTOK];
__device__ float g_rsh  [NTOK];

// decoupled-lookback state
__device__ int   g_ticket;
__device__ int   g_state[NCHAIN*NPOS];
__device__ float g_aggv [NCHAIN*NPOS*64];
__device__ float g_incv [NCHAIN*NPOS*64];

// fragment-major activations
__device__ uint4 g_rf[NT128*16*(ASZ128/4)];
__device__ uint4 g_tf[NT128*(ASZ128/4)];

// pre-fragmented bf16 weights
__device__ uint4 g_wf_seq [NBLK*BSZ/4];
__device__ uint4 g_wf_dep [NBLK*BSZ/4];
__device__ uint4 g_wf_loc [NBLK*BSZ/4];
__device__ uint4 g_wf_lrA [NBLK*BSZ/4];
__device__ uint4 g_wf_post[NBLK*3*BSZ/4];
__device__ uint4 g_wf_lrB [16*BSZ/4];

__device__ __forceinline__ float siluf(float x) {
    return x / (1.0f + __expf(-x));
}

__device__ __forceinline__ unsigned pk(float a, float b) {
    unsigned r;
    asm("cvt.rn.bf16x2.f32 %0, %1, %2;" : "=r"(r) : "f"(b), "f"(a));
    return r;
}

__device__ __forceinline__ float decay1(const float* __restrict__ lA,
                                        const float* __restrict__ ldt, int d) {
    return fmaxf(__expf(-__expf(lA[d]) * __expf(ldt[d])), 1e-6f);
}

// ---------------- acquire/release ----------------
__device__ __forceinline__ int ld_acq(const int* p) {
    int v;
    asm volatile("ld.global.acquire.gpu.b32 %0, [%1];" : "=r"(v) : "l"(p));
    return v;
}
__device__ __forceinline__ void st_rel(int* p, int v) {
    asm volatile("st.global.release.gpu.b32 [%0], %1;" :: "l"(p), "r"(v));
}

// ---------------- cp.async helpers ----------------
__device__ __forceinline__ unsigned sptr(const void* p) {
    return (unsigned)__cvta_generic_to_shared(p);
}
__device__ __forceinline__ void cpa16(unsigned d, const void* s) {
    asm volatile("cp.async.cg.shared.global [%0], [%1], 16;" :: "r"(d), "l"(s));
}
__device__ __forceinline__ void cpa16z(unsigned d, const void* s) {
    asm volatile("cp.async.cg.shared.global [%0], [%1], 16, 0;" :: "r"(d), "l"(s));
}
__device__ __forceinline__ void cp_commit() {
    asm volatile("cp.async.commit_group;");
}
template<int N>
__device__ __forceinline__ void cp_wait() {
    asm volatile("cp.async.wait_group %0;" :: "n"(N));
}
template<int N4>
__device__ __forceinline__ void cpcopy(unsigned dsm, const uint4* __restrict__ src, int tid) {
#pragma unroll
    for (int i = tid; i < N4; i += 256) cpa16(dsm + i * 16, src + i);
}

// row-major A chunk copy: 128 tokens x 64 bf16 (128B/row), SW128 swizzle.
template<bool SHIFT>
__device__ __forceinline__ void cpA_row(unsigned dsm, const __nv_bfloat16* __restrict__ colbase,
                                        int tok0, int tid) {
#pragma unroll
    for (int it = 0; it < 4; ++it) {
        int idx = tid + it * 256;
        int row = idx >> 3;
        int c16 = idx & 7;
        unsigned dst = dsm + row * 128 + ((c16 ^ (row & 7)) << 4);
        int tok = tok0 + row;
        if (SHIFT) {
            if ((tok & (TT_SEQ - 1)) == 0) cpa16z(dst, colbase);
            else cpa16(dst, colbase + (size_t)(tok - 1) * DD + c16 * 8);
        } else {
            cpa16(dst, colbase + (size_t)tok * DD + c16 * 8);
        }
    }
}

// ---------------- bf16 MMA machinery ----------------
__device__ __forceinline__ void mma_bf16(float c[4], const unsigned a[4], const unsigned b[2]) {
    asm volatile("mma.sync.aligned.m16n8k16.row.col.f32.bf16.bf16.f32 "
        "{%0,%1,%2,%3}, {%4,%5,%6,%7}, {%8,%9}, {%0,%1,%2,%3};"
        : "+f"(c[0]), "+f"(c[1]), "+f"(c[2]), "+f"(c[3])
        : "r"(a[0]), "r"(a[1]), "r"(a[2]), "r"(a[3]), "r"(b[0]), "r"(b[1]));
}

// ldmatrix x4: A fragment (m16 tile mt, k-chunk ks) from swizzled row-major tile
__device__ __forceinline__ void ldsmA(unsigned a[4], unsigned sAbase, int mt, int ks, int lane) {
    int row = mt * 16 + (lane & 7) + ((lane & 8) ? 8 : 0);
    int ci  = ks * 2 + ((lane & 16) ? 1 : 0);
    unsigned addr = sAbase + row * 128 + ((ci ^ (row & 7)) << 4);
    asm volatile("ldmatrix.sync.aligned.m8n8.x4.shared.b16 {%0,%1,%2,%3}, [%4];"
        : "=r"(a[0]), "=r"(a[1]), "=r"(a[2]), "=r"(a[3]) : "r"(addr));
}

// g1s: M=128, 8m x 1n warps, row-major A (unchanged from R14 structure, inlined in kernel)

// g2: M=128 via 4m x 2n warps, row-major A (ldmatrix), B traffic halved
__device__ __forceinline__ void mma_g2(float acc[8][4], unsigned sAbase,
                                       const unsigned* sB, int wm, int wn, int lane) {
#pragma unroll
    for (int ks = 0; ks < 4; ks++) {
        unsigned a0[4], a1[4];
        ldsmA(a0, sAbase, wm, ks, lane);
        ldsmA(a1, sAbase, wm + 4, ks, lane);
#pragma unroll
        for (int nt = 0; nt < 4; nt++) {
            unsigned b[2];
            *reinterpret_cast<uint2*>(b) =
                *reinterpret_cast<const uint2*>(&sB[((wn * 4 + nt) * 4 + ks) * BSLOT + lane * 2]);
            mma_bf16(acc[nt], a0, b);
            mma_bf16(acc[4 + nt], a1, b);
        }
    }
}

// g4: M=128 via 4m x 2n warps, fragment-major A
__device__ __forceinline__ void mma_g4(float acc[8][4], const unsigned* sA,
                                       const unsigned* sB, int wm, int wn, int lane) {
#pragma unroll
    for (int ks = 0; ks < 4; ks++) {
        unsigned a0[4], a1[4];
        *reinterpret_cast<uint4*>(a0) =
            *reinterpret_cast<const uint4*>(&sA[(wm * 4 + ks) * ASLOT + lane * 4]);
        *reinterpret_cast<uint4*>(a1) =
            *reinterpret_cast<const uint4*>(&sA[((wm + 4) * 4 + ks) * ASLOT + lane * 4]);
#pragma unroll
        for (int nt = 0; nt < 4; nt++) {
            unsigned b[2];
            *reinterpret_cast<uint2*>(b) =
                *reinterpret_cast<const uint2*>(&sB[((wn * 4 + nt) * 4 + ks) * BSLOT + lane * 2]);
            mma_bf16(acc[nt], a0, b);
            mma_bf16(acc[4 + nt], a1, b);
        }
    }
}

// g3: M=64 fragment-major (unchanged)
__device__ __forceinline__ void mma_chunk64(float acc[4][4], const unsigned* sA,
                                            const unsigned* sB, int wm, int wn, int lane) {
#pragma unroll
    for (int ks = 0; ks < 4; ks++) {
        unsigned a[4];
        *reinterpret_cast<uint4*>(a) =
            *reinterpret_cast<const uint4*>(&sA[(wm * 4 + ks) * ASLOT + lane * 4]);
#pragma unroll
        for (int nt = 0; nt < 4; nt++) {
            unsigned b[2];
            *reinterpret_cast<uint2*>(b) =
                *reinterpret_cast<const uint2*>(&sB[((wn * 4 + nt) * 4 + ks) * BSLOT + lane * 2]);
            mma_bf16(acc[nt], a, b);
        }
    }
}

__device__ __forceinline__ void scale_acc4(float acc[8][4], float a0, float b0,
                                           float a1, float b1) {
#pragma unroll
    for (int nt = 0; nt < 4; nt++) {
        acc[nt][0] *= a0; acc[nt][1] *= a0;
        acc[nt][2] *= b0; acc[nt][3] *= b0;
        acc[4 + nt][0] *= a1; acc[4 + nt][1] *= a1;
        acc[4 + nt][2] *= b1; acc[4 + nt][3] *= b1;
    }
}

// ---------------- prep: flags + weight fragmentation + x stats ----------------
__global__ void __launch_bounds__(256) k_prep(const float* __restrict__ x,
                                              const float* __restrict__ wseq,
                                              const float* __restrict__ wdep,
                                              const float* __restrict__ wloc,
                                              const float* __restrict__ lrA,
                                              const float* __restrict__ wpost,
                                              const float* __restrict__ lrB) {
    int tid = threadIdx.x;
    if (blockIdx.x == 0) {
        if (tid == 0) g_ticket = 0;
        for (int i = tid; i < NCHAIN * NPOS; i += 256) g_state[i] = 0;
    }
    if (blockIdx.x < 128) {
        int t = blockIdx.x;
        const float* src;
        unsigned* dst;
        int rs;
        if (t < 16)       { src = wseq + (size_t)t * 4096; dst = (unsigned*)g_wf_seq + t * BSZ; rs = 64; }
        else if (t < 32)  { int b = t - 16; src = wdep + (size_t)b * 4096; dst = (unsigned*)g_wf_dep + b * BSZ; rs = 64; }
        else if (t < 48)  { int b = t - 32; src = wloc + (size_t)b * 4096; dst = (unsigned*)g_wf_loc + b * BSZ; rs = 64; }
        else if (t < 64)  { int b = t - 48; src = lrA + (size_t)b * 4096;  dst = (unsigned*)g_wf_lrA + b * BSZ; rs = 64; }
        else if (t < 112) { int i = t - 64; int b = i / 3, kt = i % 3;
                            src = wpost + (size_t)b * 64 * BIP + kt * 64;
                            dst = (unsigned*)g_wf_post + i * BSZ; rs = BIP; }
        else              { int kt = t - 112; src = lrB + kt * 64; dst = (unsigned*)g_wf_lrB + kt * BSZ; rs = DD; }
#pragma unroll
        for (int it = 0; it < 4; ++it) {
            int idx = tid + it * 256;
            int n  = idx >> 4;
            int k0 = (idx & 15) << 2;
            float4 v = *reinterpret_cast<const float4*>(src + (size_t)n * rs + k0);
            int nt = n >> 3, g = n & 7;
            int ks = k0 >> 4, kk = k0 & 15, hi = kk >> 3, t0 = (kk & 7) >> 1;
            unsigned* p = &dst[(nt * 4 + ks) * BSLOT + (g * 4 + t0) * 2 + hi];
            p[0] = pk(v.x, v.y);
            p[2] = pk(v.z, v.w);
        }
    } else {
        int w = tid >> 5, lane = tid & 31;
        int tok = (blockIdx.x - 128) * 8 + w;
        const float4* xr = reinterpret_cast<const float4*>(x + (size_t)tok * DD);
        float4 v[8];
        float ss = 0.0f;
#pragma unroll
        for (int i = 0; i < 8; i++) {
            v[i] = xr[lane + i * 32];
            ss += v[i].x * v[i].x + v[i].y * v[i].y + v[i].z * v[i].z + v[i].w * v[i].w;
        }
#pragma unroll
        for (int off = 16; off > 0; off >>= 1) ss += __shfl_xor_sync(0xffffffffu, ss, off);
        ss = __shfl_sync(0xffffffffu, ss, 0);
        float sc = rsqrtf(ss * (1.0f / DD) + EPSV);
        if (lane == 0) g_rsx[tok] = sc;
        uint2* xo = reinterpret_cast<uint2*>(g_xn + (size_t)tok * DD);
#pragma unroll
        for (int i = 0; i < 8; i++) {
            uint2 o;
            o.x = pk(v[i].x * sc, v[i].y * sc);
            o.y = pk(v[i].z * sc, v[i].w * sc);
            xo[lane + i * 32] = o;
        }
    }
}

// ---------------- gain helper ----------------
__device__ __forceinline__ float gain_of(int gch, float Kf, const float* __restrict__ lAd,
                                         const float* __restrict__ ldtd) {
    if (gch < NMEM) return Kf;
    float a1 = __expf(-__expf(lAd[gch - NMEM]) * __expf(ldtd[gch - NMEM]));
    float om = 1.0f - a1;
    if (fabsf(om) < 1e-6f) return Kf;
    return (1.0f - __expf(Kf * __logf(a1))) / fmaxf(om, 1e-8f);
}

// ---------------- G1S: GEMMs (ldmatrix A) + single-pass scan -> g_hn ----------------
#define G1SMEM (13248 * 4)

__global__ void __launch_bounds__(256) k_g1s(const float* __restrict__ lAd,
                                             const float* __restrict__ ldtd,
                                             const float* __restrict__ lAs,
                                             const float* __restrict__ ldts,
                                             const int* __restrict__ kptr) {
    extern __shared__ __align__(16) unsigned dyn[];
    __shared__ int s_ticket;
    int tid = threadIdx.x, lane = tid & 31, w = tid >> 5;

    if (tid == 0) s_ticket = atomicAdd(&g_ticket, 1);
    __syncthreads();
    int ticket = s_ticket;
    int chain = ticket & (NCHAIN - 1);
    int pos   = ticket >> 6;
    int b = chain >> 4, blk = chain & 15;
    int tok0 = (b * NPOS + pos) * 128;

    unsigned* sB1 = dyn + ARSZ;
    unsigned* sB2 = dyn + ARSZ + BSZ;

    cpA_row<false>(sptr(dyn), g_xn + blk * 64, tok0, tid);
    cpcopy<528>(sptr(sB1), g_wf_seq + (size_t)blk * 528, tid);
    cpcopy<528>(sptr(sB2), g_wf_dep + (size_t)blk * 528, tid);
    cp_commit();
    cp_wait<0>();
    __syncthreads();

    float as_[8][4] = {}, ad_[8][4] = {};
    unsigned sAbase = sptr(dyn);
#pragma unroll
    for (int ks = 0; ks < 4; ks++) {
        unsigned a[4];
        ldsmA(a, sAbase, w, ks, lane);
#pragma unroll
        for (int nt = 0; nt < 8; nt++) {
            int off = (nt * 4 + ks) * BSLOT + lane * 2;
            unsigned bb[2];
            *reinterpret_cast<uint2*>(bb) = *reinterpret_cast<const uint2*>(&sB1[off]);
            mma_bf16(as_[nt], a, bb);
            *reinterpret_cast<uint2*>(bb) = *reinterpret_cast<const uint2*>(&sB2[off]);
            mma_bf16(ad_[nt], a, bb);
        }
    }
    __syncthreads();                  // staging dead; alias scan buffers

    float*    sD  = reinterpret_cast<float*>(dyn);           // [128][66] fp32
    unsigned* sHD = dyn + 8448;                              // [128][33] bf16x2
    float*    sS  = reinterpret_cast<float*>(dyn + 12672);   // [4][64]
    float*    sQ  = sS + 256;                                // [4][64]
    float*    sC  = sQ + 256;                                // [64]

    // epilogue: silu -> drive (fp32, smem) ; gain*silu -> hd (bf16x2, smem)
    {
        float Kf = (float)(*kptr);
        int g = lane >> 2, t = lane & 3;
        int rl0 = w * 16 + g;
#pragma unroll
        for (int nt = 0; nt < 8; nt++) {
            int nl = nt * 8 + t * 2;
            int gch = blk * 64 + nl;
            float gn0 = gain_of(gch, Kf, lAd, ldtd);
            float gn1 = gain_of(gch + 1, Kf, lAd, ldtd);
            *reinterpret_cast<float2*>(&sD[rl0 * SDS + nl]) =
                make_float2(siluf(as_[nt][0]), siluf(as_[nt][1]));
            *reinterpret_cast<float2*>(&sD[(rl0 + 8) * SDS + nl]) =
                make_float2(siluf(as_[nt][2]), siluf(as_[nt][3]));
            sHD[rl0 * 33 + (nl >> 1)] =
                pk(gn0 * siluf(ad_[nt][0]), gn1 * siluf(ad_[nt][1]));
            sHD[(rl0 + 8) * 33 + (nl >> 1)] =
                pk(gn0 * siluf(ad_[nt][2]), gn1 * siluf(ad_[nt][3]));
        }
    }
    __syncthreads();

    // scan thread mapping: ch = tid & 63, q = tid >> 6
    int ch = tid & 63, q = tid >> 6;
    int gch = blk * 64 + ch;
    float a  = decay1(lAs, ldts, gch);
    float la = __logf(a);
    float a32 = __expf(32.0f * la);
    float aT  = __expf(128.0f * la);

    // local quarter scan (in place)
    {
        float y = 0.0f;
        int base = q * 32;
#pragma unroll 8
        for (int s = 0; s < 32; s++) {
            float* p = &sD[(base + s) * SDS + ch];
            y = fmaf(a, y, *p);
            *p = y;
        }
        sS[q * 64 + ch] = y;
    }
    __syncthreads();

    // quarter combine + aggregate publish
    float agg = 0.0f;
    if (tid < 64) {
        float C = 0.0f;
#pragma unroll
        for (int q2 = 0; q2 < 4; q2++) {
            sQ[q2 * 64 + tid] = C;
            C = fmaf(C, a32, sS[q2 * 64 + tid]);
        }
        agg = C;
        g_aggv[(size_t)(chain * NPOS + pos) * 64 + tid] = agg;
    }
    __syncthreads();
    if (tid == 0) {
        __threadfence();
        st_rel(&g_state[chain * NPOS + pos], 1);
    }

    // lookback
    if (tid < 64) {
        float carry = 0.0f;
        if (pos > 0) {
            float f = 1.0f;
            int p = pos - 1;
            while (true) {
                int st;
                do { st = ld_acq(&g_state[chain * NPOS + p]); } while (st == 0);
                if (st == 2) {
                    carry = fmaf(f, g_incv[(size_t)(chain * NPOS + p) * 64 + tid], carry);
                    break;
                }
                carry = fmaf(f, g_aggv[(size_t)(chain * NPOS + p) * 64 + tid], carry);
                f *= aT;
                if (--p < 0) break;
            }
        }
        sC[tid] = carry;
        if (pos < NPOS - 1)
            g_incv[(size_t)(chain * NPOS + pos) * 64 + tid] = fmaf(carry, aT, agg);
    }
    __syncthreads();
    if (tid == 0 && pos < NPOS - 1) {
        __threadfence();
        st_rel(&g_state[chain * NPOS + pos], 2);
    }

    // final combine: h = local + eff_carry * a^(s+1) + hd
    {
        float carry = sC[ch];
        float a64 = a32 * a32;
        float aq = (q == 0) ? 1.0f : (q == 1) ? a32 : (q == 2) ? a64 : a64 * a32;
        float eff = fmaf(carry, aq, sQ[q * 64 + ch]);
        float pw = eff * a;
        int base = q * 32;
#pragma unroll 8
        for (int s = 0; s < 32; s++) {
            int row = base + s;
            unsigned hu = sHD[row * 33 + (ch >> 1)];
            float2 hp = __bfloat1622float2(*reinterpret_cast<__nv_bfloat162*>(&hu));
            float hdv = (ch & 1) ? hp.y : hp.x;
            float* p = &sD[row * SDS + ch];
            *p = *p + pw + hdv;
            pw *= a;
        }
    }
    __syncthreads();

    // pack + coalesced store of h -> g_hn
#pragma unroll
    for (int it = 0; it < 16; it++) {
        int idx = tid + it * 256;
        int row = idx >> 5;
        int c2  = idx & 31;
        float h0 = sD[row * SDS + c2 * 2];
        float h1 = sD[row * SDS + c2 * 2 + 1];
        *reinterpret_cast<unsigned*>(&g_hn[(size_t)(tok0 + row) * DD + blk * 64 + c2 * 2]) =
            pk(h0, h1);
    }
}

// ---------------- rstd: warp-per-token over g_hn -> g_rsh ----------------
__global__ void __launch_bounds__(256) k_rstd() {
    int w = threadIdx.x >> 5, lane = threadIdx.x & 31;
    int tok = blockIdx.x * 8 + w;
    const uint4* hr = reinterpret_cast<const uint4*>(g_hn + (size_t)tok * DD);
    float ss = 0.0f;
#pragma unroll
    for (int i = 0; i < 4; i++) {
        uint4 u = hr[lane + i * 32];
        float2 a0 = __bfloat1622float2(*reinterpret_cast<__nv_bfloat162*>(&u.x));
        float2 a1 = __bfloat1622float2(*reinterpret_cast<__nv_bfloat162*>(&u.y));
        float2 a2 = __bfloat1622float2(*reinterpret_cast<__nv_bfloat162*>(&u.z));
        float2 a3 = __bfloat1622float2(*reinterpret_cast<__nv_bfloat162*>(&u.w));
        ss += a0.x * a0.x + a0.y * a0.y + a1.x * a1.x + a1.y * a1.y
            + a2.x * a2.x + a2.y * a2.y + a3.x * a3.x + a3.y * a3.y;
    }
#pragma unroll
    for (int off = 16; off > 0; off >>= 1) ss += __shfl_xor_sync(0xffffffffu, ss, off);
    if (lane == 0) g_rsh[tok] = rsqrtf(ss * (1.0f / DD) + EPSV);
}

// ---------------- G2: fully-async A, 4m x 2n warps, acc-side rsh ----------------
__device__ __forceinline__ void g2_cpA(unsigned dsm, int tok0, int gc, int tid) {
    if (gc < 16)      cpA_row<false>(dsm, g_hn + gc * 64, tok0, tid);
    else if (gc < 32) cpA_row<false>(dsm, g_xn + (gc - 16) * 64, tok0, tid);
    else              cpA_row<true >(dsm, g_xn + (gc - 32) * 64, tok0, tid);
}

#define G2SMEM ((2 * ARSZ + 2 * BSZ) * 4)   // 49664 bytes

__global__ void __launch_bounds__(256, 4) k_g2() {
    extern __shared__ __align__(16) unsigned dsm[];
    unsigned* sA0 = dsm;
    unsigned* sA1 = dsm + ARSZ;
    unsigned* sB0 = dsm + 2 * ARSZ;
    unsigned* sB1 = sB0 + BSZ;
    int blk = blockIdx.y;
    int tok0 = blockIdx.x * 128;
    int tid = threadIdx.x, lane = tid & 31, w = tid >> 5;
    int wm = w & 3, wn = w >> 2;
    const uint4* wp = g_wf_post + (size_t)(blk * 3) * 528;
    int gc0 = blk * 3;

    g2_cpA(sptr(sA0), tok0, gc0 + 0, tid);
    cpcopy<528>(sptr(sB0), wp, tid);
    cp_commit();                              // group0: A0 + B0
    g2_cpA(sptr(sA1), tok0, gc0 + 1, tid);
    cpcopy<528>(sptr(sB1), wp + 528, tid);
    cp_commit();                              // group1: A1 + B1

    int g = lane >> 2, t = lane & 3;
    int r0 = tok0 + wm * 16 + g;
    float rsh_a0 = g_rsh[r0];
    float rsh_b0 = g_rsh[r0 + 8];
    float rsh_a1 = g_rsh[r0 + 64];
    float rsh_b1 = g_rsh[r0 + 72];
    int hnc = 16 - gc0;
    hnc = hnc < 0 ? 0 : (hnc > 3 ? 3 : hnc);

    float acc[8][4] = {};
    cp_wait<1>();
    __syncthreads();
    mma_g2(acc, sptr(sA0), sB0, wm, wn, lane);
    if (hnc == 1) scale_acc4(acc, rsh_a0, rsh_b0, rsh_a1, rsh_b1);
    __syncthreads();

    g2_cpA(sptr(sA0), tok0, gc0 + 2, tid);
    cpcopy<528>(sptr(sB0), wp + 1056, tid);
    cp_commit();                              // group2: A2 + B2

    cp_wait<1>();
    __syncthreads();
    mma_g2(acc, sptr(sA1), sB1, wm, wn, lane);
    if (hnc == 2) scale_acc4(acc, rsh_a0, rsh_b0, rsh_a1, rsh_b1);
    __syncthreads();

    cp_wait<0>();
    __syncthreads();
    mma_g2(acc, sptr(sA0), sB0, wm, wn, lane);
    if (hnc == 3) scale_acc4(acc, rsh_a0, rsh_b0, rsh_a1, rsh_b1);

    // epilogue -> g_rf (A fragment layout): warp owns m-tiles {wm, wm+4}, n-cols wn*32..
    unsigned* rf = (unsigned*)g_rf + ((size_t)((tok0 >> 7) * 16 + blk)) * ASZ128;
#pragma unroll
    for (int mi = 0; mi < 2; mi++) {
        int mt = wm + mi * 4;
#pragma unroll
        for (int nt = 0; nt < 4; nt++) {
            int ng = wn * 4 + nt;
            int ks = ng >> 1, hi = ng & 1;
            unsigned* p = rf + (mt * 4 + ks) * ASLOT + (g * 4 + t) * 4 + 2 * hi;
            float* av = acc[mi * 4 + nt];
            p[0] = pk(siluf(av[0]), siluf(av[1]));
            p[1] = pk(siluf(av[2]), siluf(av[3]));
        }
    }
}

// ---------------- G3: t = r @ lr_B^T (M=64, 2-stage cp.async pipeline) ----------------
__device__ __forceinline__ void g3_issue(unsigned dA, unsigned dB, int slab16, int halfoff,
                                         int kt, int tid) {
    cpcopy<528>(dA, g_rf + (size_t)(slab16 + kt) * 1056 + halfoff, tid);
    cpcopy<528>(dB, g_wf_lrB + (size_t)kt * 528, tid);
    cp_commit();
}

__global__ void __launch_bounds__(256) k_g3() {
    __shared__ __align__(16) unsigned smem[2 * ASZ64 + 2 * BSZ];
    unsigned* sAb[2] = { smem, smem + ASZ64 };
    unsigned* sBb[2] = { smem + 2 * ASZ64, smem + 2 * ASZ64 + BSZ };
    int tok0 = blockIdx.x * 64;
    int tid = threadIdx.x, lane = tid & 31, w = tid >> 5, wm = w & 3, wn = w >> 2;
    int slab16 = (tok0 >> 7) * 16;
    int halfoff = ((tok0 >> 6) & 1) * 528;

    g3_issue(sptr(sAb[0]), sptr(sBb[0]), slab16, halfoff, 0, tid);
    g3_issue(sptr(sAb[1]), sptr(sBb[1]), slab16, halfoff, 1, tid);

    float acc[4][4] = {};
#pragma unroll
    for (int kt = 0; kt < 16; kt++) {
        if (kt < 15) cp_wait<1>(); else cp_wait<0>();
        __syncthreads();
        mma_chunk64(acc, sAb[kt & 1], sBb[kt & 1], wm, wn, lane);
        __syncthreads();
        if (kt + 2 < 16)
            g3_issue(sptr(sAb[kt & 1]), sptr(sBb[kt & 1]), slab16, halfoff, kt + 2, tid);
    }

    int g = lane >> 2, t = lane & 3;
    int mtg = ((tok0 & 64) >> 4) + wm;
    unsigned* tf = (unsigned*)g_tf + (size_t)(tok0 >> 7) * ASZ128;
#pragma unroll
    for (int nt = 0; nt < 4; nt++) {
        int ng = wn * 4 + nt;
        int ks = ng >> 1, hi = ng & 1;
        unsigned* p = tf + (mtg * 4 + ks) * ASLOT + (g * 4 + t) * 4 + 2 * hi;
        p[0] = pk(acc[nt][0], acc[nt][1]);
        p[1] = pk(acc[nt][2], acc[nt][3]);
    }
}

// ---------------- G4: out = x + bd(r, w_local) + t @ lr_A^T (M=128, 4m x 2n) ----------------
#define G4SMEM (2 * (ASZ128 + BSZ) * 4)

__global__ void __launch_bounds__(256, 4) k_g4(const float* __restrict__ x,
                                               float* __restrict__ out) {
    extern __shared__ __align__(16) unsigned dsm[];
    unsigned* sA0 = dsm;
    unsigned* sB0 = dsm + ASZ128;
    unsigned* sA1 = dsm + ASZ128 + BSZ;
    unsigned* sB1 = dsm + 2 * ASZ128 + BSZ;
    int blk = blockIdx.y;
    int tok0 = blockIdx.x * 128;
    int tid = threadIdx.x, lane = tid & 31, w = tid >> 5;
    int wm = w & 3, wn = w >> 2;
    int slab16 = (tok0 >> 7) * 16;

    cpcopy<1056>(sptr(sA0), g_rf + (size_t)(slab16 + blk) * 1056, tid);
    cpcopy<528>(sptr(sB0), g_wf_loc + (size_t)blk * 528, tid);
    cp_commit();
    cpcopy<1056>(sptr(sA1), g_tf + (size_t)(tok0 >> 7) * 1056, tid);
    cpcopy<528>(sptr(sB1), g_wf_lrA + (size_t)blk * 528, tid);
    cp_commit();

    float acc[8][4] = {};
    cp_wait<1>();
    __syncthreads();
    mma_g4(acc, sA0, sB0, wm, wn, lane);
    cp_wait<0>();
    __syncthreads();
    mma_g4(acc, sA1, sB1, wm, wn, lane);

    int g = lane >> 2, t = lane & 3;
#pragma unroll
    for (int mi = 0; mi < 2; mi++) {
        int r0 = tok0 + (wm + mi * 4) * 16 + g;
#pragma unroll
        for (int nt = 0; nt < 4; nt++) {
            int n = blk * 64 + (wn * 4 + nt) * 8 + t * 2;
            size_t i0 = (size_t)r0 * DD + n;
            size_t i1 = (size_t)(r0 + 8) * DD + n;
            float* av = acc[mi * 4 + nt];
            float2 x0 = *reinterpret_cast<const float2*>(&x[i0]);
            float2 x1 = *reinterpret_cast<const float2*>(&x[i1]);
            *reinterpret_cast<float2*>(&out[i0]) = make_float2(x0.x + av[0], x0.y + av[1]);
            *reinterpret_cast<float2*>(&out[i1]) = make_float2(x1.x + av[2], x1.y + av[3]);
        }
    }
}

// ---------------- launch ----------------
extern "C" void kernel_launch(void* const* d_in, const int* in_sizes, int n_in,
                              void* d_out, int out_size) {
    const float* x    = (const float*)d_in[0];
    const int*   actk = (const int*)  d_in[1];
    const float* wseq = (const float*)d_in[2];
    const float* wdep = (const float*)d_in[3];
    const float* wpost= (const float*)d_in[4];
    const float* wloc = (const float*)d_in[5];
    const float* lrA  = (const float*)d_in[6];
    const float* lrB  = (const float*)d_in[7];
    const float* lAs  = (const float*)d_in[8];
    const float* ldts = (const float*)d_in[9];
    const float* lAd  = (const float*)d_in[10];
    const float* ldtd = (const float*)d_in[11];
    float* out = (float*)d_out;

    static bool attr_done = false;
    if (!attr_done) {
        cudaFuncSetAttribute(k_g1s, cudaFuncAttributeMaxDynamicSharedMemorySize, G1SMEM);
        cudaFuncSetAttribute(k_g2,  cudaFuncAttributeMaxDynamicSharedMemorySize, G2SMEM);
        cudaFuncSetAttribute(k_g4,  cudaFuncAttributeMaxDynamicSharedMemorySize, G4SMEM);
        attr_done = true;
    }

    dim3 gGemm(NTOK / 128, NBLK);    // (128, 16)

    k_prep<<<128 + NTOK / 8, 256>>>(x, wseq, wdep, wloc, lrA, wpost, lrB);
    k_g1s<<<NT128 * 16, 256, G1SMEM>>>(lAd, ldtd, lAs, ldts, actk);
    k_rstd<<<NTOK / 8, 256>>>();
    k_g2<<<gGemm, 256, G2SMEM>>>();
    k_g3<<<NTOK / 64, 256>>>();
    k_g4<<<gGemm, 256, G4SMEM>>>(x, out);
}